// round 4
// baseline (speedup 1.0000x reference)
#include <cuda_runtime.h>
#include <cuda_bf16.h>

// TensorProductScatter: per-edge e3nn tensor product (L=0/L=1 channels, MUL=32)
// followed by segment-sum over edge_dst.
//
// Strategy: warp-per-edge. lane = channel u. Stage the 352-float edge feature
// row in shared memory, then flush with red.global.add.v4.f32 (16B vector
// reductions, 4x fewer L2 atomic ops than scalar atomicAdd).
// edge_weight is streamed with __ldcs so the x table (25.6 MB) and the output
// region (70.4 MB) stay resident in L2 (126 MB).
//
// NOTE: JAX default config disables x64, so edge_dst/edge_src arrive as int32
// despite the reference's dtype=jnp.int64 annotation.

#define MULC 32
#define ROWF 352            // 32 + 96 + 96 + 32 + 96
#define WARPS_PER_BLOCK 8

__device__ __forceinline__ void red_add_v4(float* p, float4 v) {
    asm volatile("red.global.add.v4.f32 [%0], {%1, %2, %3, %4};"
                 :: "l"(p), "f"(v.x), "f"(v.y), "f"(v.z), "f"(v.w)
                 : "memory");
}

__global__ void tps_zero_kernel(float4* __restrict__ out, int n4) {
    int i = blockIdx.x * blockDim.x + threadIdx.x;
    if (i < n4) out[i] = make_float4(0.f, 0.f, 0.f, 0.f);
}

__global__ __launch_bounds__(WARPS_PER_BLOCK * 32)
void tps_scatter_kernel(const float* __restrict__ x,
                        const float* __restrict__ edge_attr,
                        const float* __restrict__ edge_weight,
                        const int*   __restrict__ edge_dst,
                        const int*   __restrict__ edge_src,
                        float*       __restrict__ out,
                        int E) {
    __shared__ __align__(16) float sm[WARPS_PER_BLOCK][ROWF];

    const int wb   = threadIdx.x >> 5;
    const int lane = threadIdx.x & 31;
    const long long e = (long long)blockIdx.x * WARPS_PER_BLOCK + wb;
    if (e >= E) return;

    // Uniform (warp-broadcast) loads
    const int s = edge_src[e];
    const int d = edge_dst[e];
    const float4 a = *reinterpret_cast<const float4*>(edge_attr + 4 * e);
    const float a0 = a.x, a1x = a.y, a1y = a.z, a1z = a.w;

    // Gather this edge's source node features (L2-resident table)
    const float* xrow = x + (long long)s * (4 * MULC);
    const float xs0 = __ldg(xrow + lane);
    const float x1a = __ldg(xrow + MULC + 3 * lane + 0);
    const float x1b = __ldg(xrow + MULC + 3 * lane + 1);
    const float x1c = __ldg(xrow + MULC + 3 * lane + 2);

    // Streaming weight loads (evict-first: protect L2 for x + out)
    const float* wrow = edge_weight + e * (5 * MULC);
    const float w0 = __ldcs(wrow + 0 * MULC + lane);
    const float w1 = __ldcs(wrow + 1 * MULC + lane);
    const float w2 = __ldcs(wrow + 2 * MULC + lane);
    const float w3 = __ldcs(wrow + 3 * MULC + lane);
    const float w4 = __ldcs(wrow + 4 * MULC + lane);

    const float INV_SQRT3 = 0.5773502691896258f;   // 1/sqrt(3)
    const float INV_SQRT2 = 0.7071067811865476f;   // 1/sqrt(2)

    // o0 = w0 * xs0 * a0
    const float o0 = w0 * xs0 * a0;
    // o1[k] = w1 * xs0 * a1[k]
    const float w1x = w1 * xs0;
    const float o1x = w1x * a1x, o1y = w1x * a1y, o1z = w1x * a1z;
    // o2[k] = w2 * xs1[k] * a0
    const float w2a = w2 * a0;
    const float o2x = w2a * x1a, o2y = w2a * x1b, o2z = w2a * x1c;
    // o3 = w3 * dot(xs1, a1) / sqrt3
    const float dot = x1a * a1x + x1b * a1y + x1c * a1z;
    const float o3 = w3 * dot * INV_SQRT3;
    // o4[k] = w4 * cross(xs1, a1)[k] / sqrt2
    const float cx = x1b * a1z - x1c * a1y;
    const float cy = x1c * a1x - x1a * a1z;
    const float cz = x1a * a1y - x1b * a1x;
    const float w4s = w4 * INV_SQRT2;
    const float o4x = w4s * cx, o4y = w4s * cy, o4z = w4s * cz;

    // Stage row into shared memory (stride-3 stores: gcd(3,32)=1 -> conflict-free)
    float* r = sm[wb];
    r[lane]                 = o0;
    r[MULC + 3 * lane + 0]  = o1x;
    r[MULC + 3 * lane + 1]  = o1y;
    r[MULC + 3 * lane + 2]  = o1z;
    r[128  + 3 * lane + 0]  = o2x;
    r[128  + 3 * lane + 1]  = o2y;
    r[128  + 3 * lane + 2]  = o2z;
    r[224  + lane]          = o3;
    r[256  + 3 * lane + 0]  = o4x;
    r[256  + 3 * lane + 1]  = o4y;
    r[256  + 3 * lane + 2]  = o4z;
    __syncwarp();

    // Flush: 88 float4 chunks, coalesced vector reductions into out[dst]
    const float4* rv = reinterpret_cast<const float4*>(r);
    float* orow = out + (long long)d * ROWF;
    #pragma unroll
    for (int c = lane; c < ROWF / 4; c += 32) {
        red_add_v4(orow + 4 * c, rv[c]);
    }
}

extern "C" void kernel_launch(void* const* d_in, const int* in_sizes, int n_in,
                              void* d_out, int out_size) {
    const float* x           = (const float*)d_in[0];
    const float* edge_attr   = (const float*)d_in[1];
    const float* edge_weight = (const float*)d_in[2];
    const int*   edge_dst    = (const int*)d_in[3];
    const int*   edge_src    = (const int*)d_in[4];
    float* out = (float*)d_out;

    const int E = in_sizes[3];  // edge_dst element count

    // Zero the (poisoned) output
    int n4 = out_size / 4;
    tps_zero_kernel<<<(n4 + 255) / 256, 256>>>((float4*)out, n4);

    // One warp per edge
    int blocks = (E + WARPS_PER_BLOCK - 1) / WARPS_PER_BLOCK;
    tps_scatter_kernel<<<blocks, WARPS_PER_BLOCK * 32>>>(
        x, edge_attr, edge_weight, edge_dst, edge_src, out, E);
}